// round 13
// baseline (speedup 1.0000x reference)
#include <cuda_runtime.h>
#include <math.h>
#include <float.h>

#define SS 2048
#define DD 2048
#define NH 16
#define DN 128
#define DRp 64
#define DVp 128
#define RDIM 512
#define HIi 4
#define DIi 64
#define KTOPk 512
#define NE 4
#define DFF 8192
#define QD 192   /* DN+DR */
#define KVD 256  /* DN+DV */

// ---------------- scratch (device globals; no allocation allowed) ----------------
__device__ float g_h  [(size_t)SS*DD];
__device__ float g_q  [(size_t)SS*NH*QD];
__device__ float g_ckv[(size_t)SS*(RDIM+DRp)];
__device__ float g_c  [(size_t)SS*RDIM];
__device__ float g_kv [(size_t)SS*NH*KVD];
__device__ float g_kf [(size_t)SS*NH*QD];
__device__ float g_qi [(size_t)SS*HIi*DIi];
__device__ float g_ki [(size_t)SS*DIi];
__device__ float g_wt [(size_t)SS*HIi];
__device__ float g_o  [(size_t)SS*NH*DVp];
__device__ float g_x2 [(size_t)SS*DD];
__device__ float g_h2 [(size_t)SS*DD];
__device__ float g_rl [(size_t)SS*NE];
__device__ float g_hid[(size_t)SS*DFF];
__device__ int   g_sel[(size_t)SS*KTOPk];
__device__ int   g_nsel[SS];
__device__ int   g_cnt[NE];
__device__ float g_ps [NE];
__device__ int   g_list[NE*SS];
__device__ float g_gate[NE*SS];

// ---------------- RMSNorm ----------------
__global__ void rms_kernel(const float* __restrict__ in, int istride, int width,
                           const float* __restrict__ w, float* __restrict__ out, int ostride){
    int row = blockIdx.x;
    const float* ip = in + (size_t)row * istride;
    float ssq = 0.f;
    for (int i = threadIdx.x; i < width; i += blockDim.x){ float v = ip[i]; ssq += v*v; }
    __shared__ float red[32];
    int lane = threadIdx.x & 31, wid = threadIdx.x >> 5;
    #pragma unroll
    for (int o = 16; o; o >>= 1) ssq += __shfl_xor_sync(0xffffffffu, ssq, o);
    if (lane == 0) red[wid] = ssq;
    __syncthreads();
    if (threadIdx.x == 0){
        float tot = 0.f; int nw = blockDim.x >> 5;
        for (int i = 0; i < nw; i++) tot += red[i];
        red[0] = rsqrtf(tot / (float)width + 1e-6f);
    }
    __syncthreads();
    float sc = red[0];
    float* op = out + (size_t)row * ostride;
    for (int i = threadIdx.x; i < width; i += blockDim.x) op[i] = ip[i] * sc * w[i];
}

// ---------------- legacy fp32 SGEMM (kept for small indexer/router GEMMs) ----------------
template<int EPI, bool GATHER>
__global__ void __launch_bounds__(256)
sgemm_k(const float* __restrict__ A, const float* __restrict__ B,
        float* __restrict__ C, int M, int N, int K,
        const int* __restrict__ rowidx, const int* __restrict__ cntp,
        const float* __restrict__ bias, const float* __restrict__ addp,
        const float* __restrict__ gatep)
{
    int Meff = cntp ? *cntp : M;
    int bm = blockIdx.y, bn = blockIdx.x;
    if (bm * 128 >= Meff) return;

    __shared__ float As[8][128];
    __shared__ float Bs[8][128];

    int tid = threadIdx.x;
    int tx = tid & 15, ty = tid >> 4;

    float acc[8][8];
    #pragma unroll
    for (int i = 0; i < 8; i++)
        #pragma unroll
        for (int j = 0; j < 8; j++) acc[i][j] = 0.f;

    int arow = tid >> 1, acol = (tid & 1) * 4;
    int gm = bm * 128 + arow;
    bool aok = gm < Meff;
    int asrc = aok ? (GATHER ? rowidx[gm] : gm) : 0;
    const float* Arow = A + (size_t)asrc * K;

    int brow = tid >> 5, bcol = (tid & 31) * 4;
    int gn = bn * 128 + bcol;

    for (int k0 = 0; k0 < K; k0 += 8){
        float4 av = make_float4(0.f,0.f,0.f,0.f);
        if (aok) av = *(const float4*)(Arow + k0 + acol);
        float4 bv;
        if (gn + 3 < N){
            bv = *(const float4*)(B + (size_t)(k0 + brow) * N + gn);
        } else {
            float t0 = (gn+0 < N) ? B[(size_t)(k0+brow)*N + gn+0] : 0.f;
            float t1 = (gn+1 < N) ? B[(size_t)(k0+brow)*N + gn+1] : 0.f;
            float t2 = (gn+2 < N) ? B[(size_t)(k0+brow)*N + gn+2] : 0.f;
            float t3 = (gn+3 < N) ? B[(size_t)(k0+brow)*N + gn+3] : 0.f;
            bv = make_float4(t0,t1,t2,t3);
        }
        __syncthreads();
        As[acol+0][arow] = av.x; As[acol+1][arow] = av.y;
        As[acol+2][arow] = av.z; As[acol+3][arow] = av.w;
        *(float4*)(&Bs[brow][bcol]) = bv;
        __syncthreads();

        #pragma unroll
        for (int kk = 0; kk < 8; kk++){
            float4 a0 = *(const float4*)(&As[kk][ty*8]);
            float4 a1 = *(const float4*)(&As[kk][ty*8+4]);
            float4 b0 = *(const float4*)(&Bs[kk][tx*8]);
            float4 b1 = *(const float4*)(&Bs[kk][tx*8+4]);
            float a[8] = {a0.x,a0.y,a0.z,a0.w,a1.x,a1.y,a1.z,a1.w};
            float b[8] = {b0.x,b0.y,b0.z,b0.w,b1.x,b1.y,b1.z,b1.w};
            #pragma unroll
            for (int i = 0; i < 8; i++)
                #pragma unroll
                for (int j = 0; j < 8; j++)
                    acc[i][j] = fmaf(a[i], b[j], acc[i][j]);
        }
    }

    int cm = bm * 128 + ty * 8, cn = bn * 128 + tx * 8;
    #pragma unroll
    for (int i = 0; i < 8; i++){
        int row = cm + i;
        if (row >= Meff) break;
        #pragma unroll
        for (int j = 0; j < 8; j++){
            int col = cn + j;
            if (col >= N) break;
            float v = acc[i][j];
            if (EPI == 0){
                C[(size_t)row * N + col] = v;
            } else if (EPI == 1){
                C[(size_t)row * N + col] = v + addp[(size_t)row * N + col];
            } else if (EPI == 2){
                v += bias[col];
                C[(size_t)row * N + col] = 0.5f * v * (1.0f + erff(v * 0.7071067811865475f));
            } else {
                int tok = rowidx[row];
                atomicAdd(&C[(size_t)tok * N + col], gatep[row] * (v + bias[col]));
            }
        }
    }
}

// ---------------- tf32 tensor-core GEMM: 128x128x16 tile, double-buffered ----------------
__device__ __forceinline__ unsigned f2tf(float x){
    unsigned u; asm("cvt.rna.tf32.f32 %0, %1;" : "=r"(u) : "f"(x)); return u;
}

__device__ __forceinline__ void mma_tf32(float* c,
    unsigned a0, unsigned a1, unsigned a2, unsigned a3, unsigned b0, unsigned b1){
    asm volatile(
        "mma.sync.aligned.m16n8k8.row.col.f32.tf32.tf32.f32 "
        "{%0,%1,%2,%3},{%4,%5,%6,%7},{%8,%9},{%0,%1,%2,%3};"
        : "+f"(c[0]), "+f"(c[1]), "+f"(c[2]), "+f"(c[3])
        : "r"(a0), "r"(a1), "r"(a2), "r"(a3), "r"(b0), "r"(b1));
}

#define TLD 136  /* padded stride: bank = (8*kc + r) % 32 hits all banks */

template<int EPI, bool GATHER>
__global__ void __launch_bounds__(256)
tgemm_k(const float* __restrict__ A, const float* __restrict__ B,
        float* __restrict__ C, int M, int N, int K,
        const int* __restrict__ rowidx, const int* __restrict__ cntp,
        const float* __restrict__ bias, const float* __restrict__ addp,
        const float* __restrict__ gatep)
{
    int Meff = cntp ? *cntp : M;
    int bm = blockIdx.y, bn = blockIdx.x;
    if (bm * 128 >= Meff) return;

    __shared__ unsigned As[2][16][TLD];
    __shared__ unsigned Bs[2][16][TLD];

    int tid  = threadIdx.x;
    int warp = tid >> 5, lane = tid & 31;
    int wm = (warp >> 2) * 64;   // warp m-offset: 0 or 64
    int wn = (warp & 3) * 32;    // warp n-offset: 0..96
    int lr = lane >> 2, lc = lane & 3;

    float acc[4][4][4];
    #pragma unroll
    for (int a = 0; a < 4; a++)
        #pragma unroll
        for (int b = 0; b < 4; b++)
            #pragma unroll
            for (int i = 0; i < 4; i++) acc[a][b][i] = 0.f;

    // A loads: 128 rows x 16 cols; row = tid/2, col half = (tid&1)*8
    int arow = tid >> 1, acol = (tid & 1) * 8;
    int gm = bm * 128 + arow;
    bool aok = gm < Meff;
    const float* Arow = A + (size_t)(aok ? (GATHER ? rowidx[gm] : gm) : 0) * K;

    // B loads: 16 rows x 128 cols; rows tid/32 and tid/32+8, col = (tid&31)*4
    int brow = tid >> 5;
    int bcol = (tid & 31) * 4;
    int gn = bn * 128 + bcol;

    float4 av0, av1, bv0, bv1;

    auto loadAB = [&](int k0){
        if (aok){
            av0 = *(const float4*)(Arow + k0 + acol);
            av1 = *(const float4*)(Arow + k0 + acol + 4);
        } else {
            av0 = av1 = make_float4(0.f,0.f,0.f,0.f);
        }
        if (gn + 3 < N){
            bv0 = *(const float4*)(B + (size_t)(k0 + brow) * N + gn);
            bv1 = *(const float4*)(B + (size_t)(k0 + brow + 8) * N + gn);
        } else {
            const float* r0 = B + (size_t)(k0 + brow) * N;
            const float* r1 = B + (size_t)(k0 + brow + 8) * N;
            bv0.x = (gn+0 < N) ? r0[gn+0] : 0.f;
            bv0.y = (gn+1 < N) ? r0[gn+1] : 0.f;
            bv0.z = (gn+2 < N) ? r0[gn+2] : 0.f;
            bv0.w = (gn+3 < N) ? r0[gn+3] : 0.f;
            bv1.x = (gn+0 < N) ? r1[gn+0] : 0.f;
            bv1.y = (gn+1 < N) ? r1[gn+1] : 0.f;
            bv1.z = (gn+2 < N) ? r1[gn+2] : 0.f;
            bv1.w = (gn+3 < N) ? r1[gn+3] : 0.f;
        }
    };

    auto storeAB = [&](int s){
        As[s][acol+0][arow] = f2tf(av0.x);
        As[s][acol+1][arow] = f2tf(av0.y);
        As[s][acol+2][arow] = f2tf(av0.z);
        As[s][acol+3][arow] = f2tf(av0.w);
        As[s][acol+4][arow] = f2tf(av1.x);
        As[s][acol+5][arow] = f2tf(av1.y);
        As[s][acol+6][arow] = f2tf(av1.z);
        As[s][acol+7][arow] = f2tf(av1.w);
        uint4 p0 = make_uint4(f2tf(bv0.x), f2tf(bv0.y), f2tf(bv0.z), f2tf(bv0.w));
        uint4 p1 = make_uint4(f2tf(bv1.x), f2tf(bv1.y), f2tf(bv1.z), f2tf(bv1.w));
        *(uint4*)&Bs[s][brow  ][bcol] = p0;
        *(uint4*)&Bs[s][brow+8][bcol] = p1;
    };

    loadAB(0);
    storeAB(0);
    __syncthreads();

    int buf = 0;
    for (int k0 = 0; k0 < K; k0 += 16){
        bool more = (k0 + 16) < K;
        if (more) loadAB(k0 + 16);

        #pragma unroll
        for (int kk = 0; kk < 16; kk += 8){
            unsigned af[4][4], bf[4][2];
            #pragma unroll
            for (int mt = 0; mt < 4; mt++){
                int r0 = wm + mt * 16 + lr;
                af[mt][0] = As[buf][kk + lc    ][r0    ];
                af[mt][1] = As[buf][kk + lc    ][r0 + 8];
                af[mt][2] = As[buf][kk + lc + 4][r0    ];
                af[mt][3] = As[buf][kk + lc + 4][r0 + 8];
            }
            #pragma unroll
            for (int nt = 0; nt < 4; nt++){
                int c0 = wn + nt * 8 + lr;
                bf[nt][0] = Bs[buf][kk + lc    ][c0];
                bf[nt][1] = Bs[buf][kk + lc + 4][c0];
            }
            #pragma unroll
            for (int mt = 0; mt < 4; mt++)
                #pragma unroll
                for (int nt = 0; nt < 4; nt++)
                    mma_tf32(acc[mt][nt], af[mt][0], af[mt][1], af[mt][2], af[mt][3],
                             bf[nt][0], bf[nt][1]);
        }

        if (more){
            storeAB(buf ^ 1);
            __syncthreads();
            buf ^= 1;
        }
    }

    // epilogue: c[i] at (row + (i>=2)*8, col + (i&1))
    #pragma unroll
    for (int mt = 0; mt < 4; mt++){
        #pragma unroll
        for (int nt = 0; nt < 4; nt++){
            int r0 = bm * 128 + wm + mt * 16 + lr;
            int c0 = bn * 128 + wn + nt * 8 + 2 * lc;
            #pragma unroll
            for (int i = 0; i < 4; i++){
                int row = r0 + ((i >> 1) * 8);
                int col = c0 + (i & 1);
                if (row < Meff && col < N){
                    float v = acc[mt][nt][i];
                    if (EPI == 0){
                        C[(size_t)row * N + col] = v;
                    } else if (EPI == 1){
                        C[(size_t)row * N + col] = v + addp[(size_t)row * N + col];
                    } else if (EPI == 2){
                        v += bias[col];
                        C[(size_t)row * N + col] = 0.5f * v * (1.0f + erff(v * 0.7071067811865475f));
                    } else {
                        int tok = rowidx[row];
                        atomicAdd(&C[(size_t)tok * N + col], gatep[row] * (v + bias[col]));
                    }
                }
            }
        }
    }
}

// ---------------- RoPE on q (in place, cols [DN,DN+64) of each head) ----------------
__global__ void ropeq_kernel(float* __restrict__ q){
    int s = blockIdx.x, h = blockIdx.y, j = threadIdx.x; // 64 threads
    float* base = q + (size_t)s * (NH*QD) + h * QD + DN;
    __shared__ float xs[64];
    xs[j] = base[j];
    __syncthreads();
    int m = j & 31;
    float freq = (float)(1.0 / pow(10000.0, (double)m / 32.0));
    float ang = (float)s * freq;
    float sn, cs; sincosf(ang, &sn, &cs);
    float other = (j < 32) ? -xs[j + 32] : xs[j - 32];
    base[j] = xs[j] * cs + other * sn;
}

// ---------------- build k_full [S, H*192]: nope from kv, roped k_rope broadcast ----------------
__global__ void buildkf_kernel(const float* __restrict__ kv, const float* __restrict__ ckv,
                               float* __restrict__ kf){
    int s = blockIdx.x, t = threadIdx.x; // 256
    __shared__ float raw[64], kr[64];
    if (t < 64) raw[t] = ckv[(size_t)s * (RDIM + DRp) + RDIM + t];
    __syncthreads();
    if (t < 64){
        int m = t & 31;
        float freq = (float)(1.0 / pow(10000.0, (double)m / 32.0));
        float ang = (float)s * freq;
        float sn, cs; sincosf(ang, &sn, &cs);
        float other = (t < 32) ? -raw[t + 32] : raw[t - 32];
        kr[t] = raw[t] * cs + other * sn;
    }
    __syncthreads();
    for (int idx = t; idx < NH * QD; idx += 256){
        int h = idx / QD, j = idx - h * QD;
        kf[(size_t)s * (NH*QD) + idx] = (j < DN) ? kv[(size_t)s * (NH*KVD) + h*KVD + j]
                                                 : kr[j - DN];
    }
}

// ---------------- indexer scores ----------------
__global__ void idx_kernel(const float* __restrict__ qi, const float* __restrict__ ki,
                           const float* __restrict__ wt, float* __restrict__ outI){
    int qb = blockIdx.y * 16, kb = blockIdx.x * 16;
    __shared__ float sq[16][HIi*DIi];
    __shared__ float sk[16][DIi + 1];
    __shared__ float sw[16][HIi];
    int t = threadIdx.x; // 256
    for (int i = t; i < 16 * HIi * DIi; i += 256)
        sq[i >> 8][i & 255] = qi[(size_t)(qb + (i >> 8)) * (HIi*DIi) + (i & 255)];
    for (int i = t; i < 16 * DIi; i += 256)
        sk[i >> 6][i & 63] = ki[(size_t)(kb + (i >> 6)) * DIi + (i & 63)];
    if (t < 16 * HIi) sw[t >> 2][t & 3] = wt[(size_t)(qb + (t >> 2)) * HIi + (t & 3)];
    __syncthreads();
    int tq = t >> 4, tk = t & 15;
    int gq = qb + tq, gk = kb + tk;
    float res;
    if (gk > gq){
        res = -FLT_MAX;
    } else {
        res = 0.f;
        #pragma unroll
        for (int hh = 0; hh < HIi; hh++){
            float dot = 0.f;
            #pragma unroll
            for (int d = 0; d < DIi; d++) dot = fmaf(sq[tq][hh*DIi + d], sk[tk][d], dot);
            res += fmaxf(dot, 0.f) * sw[tq][hh];
        }
    }
    outI[(size_t)gq * SS + gk] = res;
}

// ---------------- per-row top-k (radix select + ascending-index tie-break) ----------------
__device__ __forceinline__ int blockScanInc(int v, int* scan, int t){
    __syncthreads();
    scan[t] = v; __syncthreads();
    for (int off = 1; off < 256; off <<= 1){
        int x = (t >= off) ? scan[t - off] : 0;
        __syncthreads();
        scan[t] += x;
        __syncthreads();
    }
    return scan[t];
}

__global__ void topk_kernel(const float* __restrict__ idxs, int* __restrict__ sel,
                            int* __restrict__ nsel){
    int q = blockIdx.x, t = threadIdx.x; // 256 threads
    int n = q + 1;
    if (n <= KTOPk){
        for (int k = t; k < n; k += 256) sel[(size_t)q * KTOPk + k] = k;
        if (t == 0) nsel[q] = n;
        return;
    }
    __shared__ unsigned su[SS];
    const float* row = idxs + (size_t)q * SS;
    for (int k = t; k < n; k += 256){
        unsigned b = __float_as_uint(row[k]);
        su[k] = (b & 0x80000000u) ? ~b : (b | 0x80000000u);
    }
    __syncthreads();

    __shared__ int hist[256];
    __shared__ int sdig, srem;
    unsigned prefix = 0, mask = 0;
    int remaining = KTOPk;
    for (int pass = 0; pass < 4; pass++){
        int shift = 24 - pass * 8;
        hist[t] = 0;
        __syncthreads();
        for (int k = t; k < n; k += 256){
            unsigned u = su[k];
            if ((u & mask) == prefix) atomicAdd(&hist[(u >> shift) & 255], 1);
        }
        __syncthreads();
        if (t == 0){
            int rem = remaining, d;
            for (d = 255; d > 0; d--){
                if (hist[d] >= rem) break;
                rem -= hist[d];
            }
            sdig = d; srem = rem;
        }
        __syncthreads();
        prefix |= ((unsigned)sdig) << shift;
        mask   |= (255u << shift);
        remaining = srem;
        __syncthreads();
    }
    unsigned uthr = prefix;
    int T = remaining;

    __shared__ int scan[256];
    __shared__ int base_eq, base_sel;
    if (t == 0){ base_eq = 0; base_sel = 0; }
    __syncthreads();
    for (int c0 = 0; c0 < n; c0 += 256){
        int k = c0 + t;
        unsigned u = (k < n) ? su[k] : 0u;
        int is_gt = (k < n) && (u > uthr);
        int is_eq = (k < n) && (u == uthr);
        int eq_inc = blockScanInc(is_eq, scan, t);
        int tie_rank = base_eq + (eq_inc - is_eq);
        int chunk_eq = scan[255];
        __syncthreads();
        int is_sel = is_gt || (is_eq && tie_rank < T);
        int sel_inc = blockScanInc(is_sel, scan, t);
        int pos = base_sel + (sel_inc - is_sel);
        int chunk_sel = scan[255];
        if (is_sel) sel[(size_t)q * KTOPk + pos] = k;
        __syncthreads();
        if (t == 0){ base_eq += chunk_eq; base_sel += chunk_sel; }
        __syncthreads();
    }
    if (t == 0) nsel[q] = KTOPk;
}

// ---------------- sparse attention over selected keys ----------------
__global__ void __launch_bounds__(128)
attn_kernel(const float* __restrict__ qf, const float* __restrict__ kf,
            const float* __restrict__ kv, const int* __restrict__ sel,
            const int* __restrict__ nsel, float* __restrict__ o){
    int s = blockIdx.x, h = blockIdx.y;
    int t = threadIdx.x;            // 128
    int w = t >> 5, lane = t & 31;
    int ns = nsel[s];

    __shared__ float qs[QD];
    __shared__ float lg[KTOPk];
    __shared__ int   ksm[KTOPk];
    __shared__ float red[4];

    for (int i = t; i < QD; i += 128) qs[i] = qf[(size_t)s * (NH*QD) + h * QD + i];
    for (int i = t; i < ns; i += 128) ksm[i] = sel[(size_t)s * KTOPk + i];
    __syncthreads();

    const float scale = 0.07216878364870323f; // 1/sqrt(192)
    for (int j = w; j < ns; j += 4){
        const float* kp = kf + (size_t)ksm[j] * (NH*QD) + h * QD;
        float d = 0.f;
        #pragma unroll
        for (int e = 0; e < 6; e++) d = fmaf(qs[lane + e*32], kp[lane + e*32], d);
        #pragma unroll
        for (int off = 16; off; off >>= 1) d += __shfl_xor_sync(0xffffffffu, d, off);
        if (lane == 0) lg[j] = d * scale;
    }
    __syncthreads();

    float m = -FLT_MAX;
    for (int i = t; i < ns; i += 128) m = fmaxf(m, lg[i]);
    #pragma unroll
    for (int off = 16; off; off >>= 1) m = fmaxf(m, __shfl_xor_sync(0xffffffffu, m, off));
    if (lane == 0) red[w] = m;
    __syncthreads();
    m = fmaxf(fmaxf(red[0], red[1]), fmaxf(red[2], red[3]));
    __syncthreads();

    float psum = 0.f;
    for (int i = t; i < ns; i += 128){
        float p = expf(lg[i] - m);
        lg[i] = p;
        psum += p;
    }
    #pragma unroll
    for (int off = 16; off; off >>= 1) psum += __shfl_xor_sync(0xffffffffu, psum, off);
    if (lane == 0) red[w] = psum;
    __syncthreads();
    float tot = red[0] + red[1] + red[2] + red[3];
    float inv = 1.f / tot;

    const float* vb = kv + h * KVD + DN;
    float a0 = 0.f, a1 = 0.f, a2 = 0.f, a3 = 0.f;
    int j = 0;
    for (; j + 3 < ns; j += 4){
        a0 = fmaf(lg[j+0], vb[(size_t)ksm[j+0] * (NH*KVD) + t], a0);
        a1 = fmaf(lg[j+1], vb[(size_t)ksm[j+1] * (NH*KVD) + t], a1);
        a2 = fmaf(lg[j+2], vb[(size_t)ksm[j+2] * (NH*KVD) + t], a2);
        a3 = fmaf(lg[j+3], vb[(size_t)ksm[j+3] * (NH*KVD) + t], a3);
    }
    for (; j < ns; j++) a0 = fmaf(lg[j], vb[(size_t)ksm[j] * (NH*KVD) + t], a0);
    o[(size_t)s * (NH*DVp) + h * DVp + t] = ((a0 + a1) + (a2 + a3)) * inv;
}

// ---------------- MoE gating ----------------
__global__ void zero_kernel(int* cnt, float* ps){
    if (threadIdx.x < NE){ cnt[threadIdx.x] = 0; ps[threadIdx.x] = 0.f; }
}

__global__ void gate_kernel(const float* __restrict__ rl, int* __restrict__ cnt,
                            float* __restrict__ ps, int* __restrict__ list,
                            float* __restrict__ gate){
    int tk = blockIdx.x * 256 + threadIdx.x;
    if (tk >= SS) return;
    float l[NE], p[NE];
    float mx = -FLT_MAX;
    #pragma unroll
    for (int e = 0; e < NE; e++){ l[e] = rl[(size_t)tk * NE + e]; mx = fmaxf(mx, l[e]); }
    float sum = 0.f;
    #pragma unroll
    for (int e = 0; e < NE; e++){ p[e] = expf(l[e] - mx); sum += p[e]; }
    #pragma unroll
    for (int e = 0; e < NE; e++) p[e] /= sum;
    int i0 = 0;
    #pragma unroll
    for (int e = 1; e < NE; e++) if (p[e] > p[i0]) i0 = e;
    int i1 = -1;
    #pragma unroll
    for (int e = 0; e < NE; e++) if (e != i0 && (i1 < 0 || p[e] > p[i1])) i1 = e;
    float g0 = p[i0], g1 = p[i1], gs = g0 + g1;
    int pos0 = atomicAdd(&cnt[i0], 1);
    list[i0 * SS + pos0] = tk; gate[i0 * SS + pos0] = g0 / gs;
    int pos1 = atomicAdd(&cnt[i1], 1);
    list[i1 * SS + pos1] = tk; gate[i1 * SS + pos1] = g1 / gs;
    #pragma unroll
    for (int e = 0; e < NE; e++) atomicAdd(&ps[e], p[e]);
}

__global__ void aux_kernel(const int* __restrict__ cnt, const float* __restrict__ ps,
                           float* __restrict__ outAux){
    float a = 0.f;
    for (int e = 0; e < NE; e++)
        a += ((float)cnt[e] / (float)SS) * (ps[e] / (float)SS);
    *outAux = (float)NE * a;
}

// ---------------- host ----------------
extern "C" void kernel_launch(void* const* d_in, const int* in_sizes, int n_in,
                              void* d_out, int out_size){
    const float* x    = (const float*)d_in[0];
    const float* n1w  = (const float*)d_in[1];
    const float* n2w  = (const float*)d_in[2];
    const float* kvnw = (const float*)d_in[3];
    const float* Wq   = (const float*)d_in[4];
    const float* Wkva = (const float*)d_in[5];
    const float* Wkvb = (const float*)d_in[6];
    const float* Wo   = (const float*)d_in[7];
    const float* Wiq  = (const float*)d_in[8];
    const float* Wik  = (const float*)d_in[9];
    const float* Wiw  = (const float*)d_in[10];
    const float* Wr   = (const float*)d_in[11];
    const float* W1   = (const float*)d_in[12];
    const float* b1   = (const float*)d_in[13];
    const float* W2   = (const float*)d_in[14];
    const float* b2   = (const float*)d_in[15];

    float* out     = (float*)d_out;
    float* out_x   = out;
    float* out_aux = out + (size_t)SS * DD;
    float* out_idx = out + (size_t)SS * DD + 1;

    float *ph, *pq, *pckv, *pc, *pkv, *pkf, *pqi, *pki, *pwt, *po, *px2, *ph2, *prl, *phid, *pgate, *pps;
    int *psel, *pnsel, *pcnt, *plist;
    cudaGetSymbolAddress((void**)&ph,   g_h);
    cudaGetSymbolAddress((void**)&pq,   g_q);
    cudaGetSymbolAddress((void**)&pckv, g_ckv);
    cudaGetSymbolAddress((void**)&pc,   g_c);
    cudaGetSymbolAddress((void**)&pkv,  g_kv);
    cudaGetSymbolAddress((void**)&pkf,  g_kf);
    cudaGetSymbolAddress((void**)&pqi,  g_qi);
    cudaGetSymbolAddress((void**)&pki,  g_ki);
    cudaGetSymbolAddress((void**)&pwt,  g_wt);
    cudaGetSymbolAddress((void**)&po,   g_o);
    cudaGetSymbolAddress((void**)&px2,  g_x2);
    cudaGetSymbolAddress((void**)&ph2,  g_h2);
    cudaGetSymbolAddress((void**)&prl,  g_rl);
    cudaGetSymbolAddress((void**)&phid, g_hid);
    cudaGetSymbolAddress((void**)&pgate,g_gate);
    cudaGetSymbolAddress((void**)&pps,  g_ps);
    cudaGetSymbolAddress((void**)&psel, g_sel);
    cudaGetSymbolAddress((void**)&pnsel,g_nsel);
    cudaGetSymbolAddress((void**)&pcnt, g_cnt);
    cudaGetSymbolAddress((void**)&plist,g_list);

    // 1. h = rms(x, norm1_w)
    rms_kernel<<<SS, 256>>>(x, DD, DD, n1w, ph, DD);
    // 2. q = h @ Wq  (tf32)
    tgemm_k<0,false><<<dim3(24,16), 256>>>(ph, Wq, pq, SS, NH*QD, DD, nullptr,nullptr,nullptr,nullptr,nullptr);
    // 3. ckv = h @ Wkva  (tf32)
    tgemm_k<0,false><<<dim3(5,16), 256>>>(ph, Wkva, pckv, SS, RDIM+DRp, DD, nullptr,nullptr,nullptr,nullptr,nullptr);
    // 4. c = rms(ckv[:, :R], kv_norm_w)
    rms_kernel<<<SS, 256>>>(pckv, RDIM+DRp, RDIM, kvnw, pc, RDIM);
    // 5. kv = c @ Wkvb  (tf32)
    tgemm_k<0,false><<<dim3(32,16), 256>>>(pc, Wkvb, pkv, SS, NH*KVD, RDIM, nullptr,nullptr,nullptr,nullptr,nullptr);
    // 6. rope on q (in place)
    ropeq_kernel<<<dim3(SS, NH), 64>>>(pq);
    // 7. k_full
    buildkf_kernel<<<SS, 256>>>(pkv, pckv, pkf);
    // 8. indexer projections (fp32 — keep top-k selection bit-identical)
    sgemm_k<0,false><<<dim3(2,16), 256>>>(ph, Wiq, pqi, SS, HIi*DIi, DD, nullptr,nullptr,nullptr,nullptr,nullptr);
    sgemm_k<0,false><<<dim3(1,16), 256>>>(ph, Wik, pki, SS, DIi, DD, nullptr,nullptr,nullptr,nullptr,nullptr);
    sgemm_k<0,false><<<dim3(1,16), 256>>>(ph, Wiw, pwt, SS, HIi, DD, nullptr,nullptr,nullptr,nullptr,nullptr);
    // 9. idx_scores (written straight into output)
    idx_kernel<<<dim3(128,128), 256>>>(pqi, pki, pwt, out_idx);
    // 10. per-row top-k selection
    topk_kernel<<<SS, 256>>>(out_idx, psel, pnsel);
    // 11. sparse attention
    attn_kernel<<<dim3(SS, NH), 128>>>(pq, pkf, pkv, psel, pnsel, po);
    // 12. x2 = x + o @ Wo  (tf32)
    tgemm_k<1,false><<<dim3(16,16), 256>>>(po, Wo, px2, SS, DD, NH*DVp, nullptr,nullptr,nullptr, x, nullptr);
    // 13. h2 = rms(x2, norm2_w)
    rms_kernel<<<SS, 256>>>(px2, DD, DD, n2w, ph2, DD);
    // 14. router logits (fp32 — keep expert selection bit-identical)
    sgemm_k<0,false><<<dim3(1,16), 256>>>(ph2, Wr, prl, SS, NE, DD, nullptr,nullptr,nullptr,nullptr,nullptr);
    // 15. gating
    zero_kernel<<<1, 32>>>(pcnt, pps);
    gate_kernel<<<(SS+255)/256, 256>>>(prl, pcnt, pps, plist, pgate);
    aux_kernel<<<1, 1>>>(pcnt, pps, out_aux);
    // 16. init output x region with x2, then scatter-add MoE  (tf32)
    cudaMemcpyAsync(out_x, px2, sizeof(float)*(size_t)SS*DD, cudaMemcpyDeviceToDevice, 0);
    for (int e = 0; e < NE; e++){
        // hid = gelu(gather(h2) @ W1[e] + b1[e])
        tgemm_k<2,true><<<dim3(64,16), 256>>>(ph2, W1 + (size_t)e*DD*DFF, phid,
                                              SS, DFF, DD,
                                              plist + e*SS, pcnt + e,
                                              b1 + (size_t)e*DFF, nullptr, nullptr);
        // out[tok] += gate * (hid @ W2[e] + b2[e])
        tgemm_k<3,false><<<dim3(16,16), 256>>>(phid, W2 + (size_t)e*DFF*DD, out_x,
                                               SS, DD, DFF,
                                               plist + e*SS, pcnt + e,
                                               b2 + (size_t)e*DD, nullptr, pgate + e*SS);
    }
}

// round 14
// speedup vs baseline: 1.0032x; 1.0032x over previous
#include <cuda_runtime.h>
#include <math.h>
#include <float.h>

#define SS 2048
#define DD 2048
#define NH 16
#define DN 128
#define DRp 64
#define DVp 128
#define RDIM 512
#define HIi 4
#define DIi 64
#define KTOPk 512
#define NE 4
#define DFF 8192
#define QD 192   /* DN+DR */
#define KVD 256  /* DN+DV */

// ---------------- scratch (device globals; no allocation allowed) ----------------
__device__ float g_h  [(size_t)SS*DD];
__device__ float g_q  [(size_t)SS*NH*QD];
__device__ float g_ckv[(size_t)SS*(RDIM+DRp)];
__device__ float g_c  [(size_t)SS*RDIM];
__device__ float g_kv [(size_t)SS*NH*KVD];
__device__ float g_kf [(size_t)SS*NH*QD];
__device__ float g_qi [(size_t)SS*HIi*DIi];
__device__ float g_ki [(size_t)SS*DIi];
__device__ float g_wt [(size_t)SS*HIi];
__device__ float g_o  [(size_t)SS*NH*DVp];
__device__ float g_x2 [(size_t)SS*DD];
__device__ float g_h2 [(size_t)SS*DD];
__device__ float g_rl [(size_t)SS*NE];
__device__ float g_hid[(size_t)SS*DFF];
__device__ int   g_sel[(size_t)SS*KTOPk];
__device__ int   g_nsel[SS];
__device__ int   g_cnt[NE];
__device__ float g_ps [NE];
__device__ int   g_list[NE*SS];
__device__ float g_gate[NE*SS];

// ---------------- RMSNorm ----------------
__global__ void rms_kernel(const float* __restrict__ in, int istride, int width,
                           const float* __restrict__ w, float* __restrict__ out, int ostride){
    int row = blockIdx.x;
    const float* ip = in + (size_t)row * istride;
    float ssq = 0.f;
    for (int i = threadIdx.x; i < width; i += blockDim.x){ float v = ip[i]; ssq += v*v; }
    __shared__ float red[32];
    int lane = threadIdx.x & 31, wid = threadIdx.x >> 5;
    #pragma unroll
    for (int o = 16; o; o >>= 1) ssq += __shfl_xor_sync(0xffffffffu, ssq, o);
    if (lane == 0) red[wid] = ssq;
    __syncthreads();
    if (threadIdx.x == 0){
        float tot = 0.f; int nw = blockDim.x >> 5;
        for (int i = 0; i < nw; i++) tot += red[i];
        red[0] = rsqrtf(tot / (float)width + 1e-6f);
    }
    __syncthreads();
    float sc = red[0];
    float* op = out + (size_t)row * ostride;
    for (int i = threadIdx.x; i < width; i += blockDim.x) op[i] = ip[i] * sc * w[i];
}

// ---------------- legacy fp32 SGEMM (kept for small indexer/router GEMMs) ----------------
template<int EPI, bool GATHER>
__global__ void __launch_bounds__(256)
sgemm_k(const float* __restrict__ A, const float* __restrict__ B,
        float* __restrict__ C, int M, int N, int K,
        const int* __restrict__ rowidx, const int* __restrict__ cntp,
        const float* __restrict__ bias, const float* __restrict__ addp,
        const float* __restrict__ gatep)
{
    int Meff = cntp ? *cntp : M;
    int bm = blockIdx.y, bn = blockIdx.x;
    if (bm * 128 >= Meff) return;

    __shared__ float As[8][128];
    __shared__ float Bs[8][128];

    int tid = threadIdx.x;
    int tx = tid & 15, ty = tid >> 4;

    float acc[8][8];
    #pragma unroll
    for (int i = 0; i < 8; i++)
        #pragma unroll
        for (int j = 0; j < 8; j++) acc[i][j] = 0.f;

    int arow = tid >> 1, acol = (tid & 1) * 4;
    int gm = bm * 128 + arow;
    bool aok = gm < Meff;
    int asrc = aok ? (GATHER ? rowidx[gm] : gm) : 0;
    const float* Arow = A + (size_t)asrc * K;

    int brow = tid >> 5, bcol = (tid & 31) * 4;
    int gn = bn * 128 + bcol;

    for (int k0 = 0; k0 < K; k0 += 8){
        float4 av = make_float4(0.f,0.f,0.f,0.f);
        if (aok) av = *(const float4*)(Arow + k0 + acol);
        float4 bv;
        if (gn + 3 < N){
            bv = *(const float4*)(B + (size_t)(k0 + brow) * N + gn);
        } else {
            float t0 = (gn+0 < N) ? B[(size_t)(k0+brow)*N + gn+0] : 0.f;
            float t1 = (gn+1 < N) ? B[(size_t)(k0+brow)*N + gn+1] : 0.f;
            float t2 = (gn+2 < N) ? B[(size_t)(k0+brow)*N + gn+2] : 0.f;
            float t3 = (gn+3 < N) ? B[(size_t)(k0+brow)*N + gn+3] : 0.f;
            bv = make_float4(t0,t1,t2,t3);
        }
        __syncthreads();
        As[acol+0][arow] = av.x; As[acol+1][arow] = av.y;
        As[acol+2][arow] = av.z; As[acol+3][arow] = av.w;
        *(float4*)(&Bs[brow][bcol]) = bv;
        __syncthreads();

        #pragma unroll
        for (int kk = 0; kk < 8; kk++){
            float4 a0 = *(const float4*)(&As[kk][ty*8]);
            float4 a1 = *(const float4*)(&As[kk][ty*8+4]);
            float4 b0 = *(const float4*)(&Bs[kk][tx*8]);
            float4 b1 = *(const float4*)(&Bs[kk][tx*8+4]);
            float a[8] = {a0.x,a0.y,a0.z,a0.w,a1.x,a1.y,a1.z,a1.w};
            float b[8] = {b0.x,b0.y,b0.z,b0.w,b1.x,b1.y,b1.z,b1.w};
            #pragma unroll
            for (int i = 0; i < 8; i++)
                #pragma unroll
                for (int j = 0; j < 8; j++)
                    acc[i][j] = fmaf(a[i], b[j], acc[i][j]);
        }
    }

    int cm = bm * 128 + ty * 8, cn = bn * 128 + tx * 8;
    #pragma unroll
    for (int i = 0; i < 8; i++){
        int row = cm + i;
        if (row >= Meff) break;
        #pragma unroll
        for (int j = 0; j < 8; j++){
            int col = cn + j;
            if (col >= N) break;
            float v = acc[i][j];
            if (EPI == 0){
                C[(size_t)row * N + col] = v;
            } else if (EPI == 1){
                C[(size_t)row * N + col] = v + addp[(size_t)row * N + col];
            } else if (EPI == 2){
                v += bias[col];
                C[(size_t)row * N + col] = 0.5f * v * (1.0f + erff(v * 0.7071067811865475f));
            } else {
                int tok = rowidx[row];
                atomicAdd(&C[(size_t)tok * N + col], gatep[row] * (v + bias[col]));
            }
        }
    }
}

// ---------------- tf32 tensor-core GEMM: 128x128x16 tile, double-buffered ----------------
__device__ __forceinline__ unsigned f2tf(float x){
    unsigned u; asm("cvt.rna.tf32.f32 %0, %1;" : "=r"(u) : "f"(x)); return u;
}

__device__ __forceinline__ void mma_tf32(float* c,
    unsigned a0, unsigned a1, unsigned a2, unsigned a3, unsigned b0, unsigned b1){
    asm volatile(
        "mma.sync.aligned.m16n8k8.row.col.f32.tf32.tf32.f32 "
        "{%0,%1,%2,%3},{%4,%5,%6,%7},{%8,%9},{%0,%1,%2,%3};"
        : "+f"(c[0]), "+f"(c[1]), "+f"(c[2]), "+f"(c[3])
        : "r"(a0), "r"(a1), "r"(a2), "r"(a3), "r"(b0), "r"(b1));
}

#define TLD 136  /* padded stride: bank = (8*kc + r) % 32 hits all banks */

template<int EPI, bool GATHER>
__global__ void __launch_bounds__(256)
tgemm_k(const float* __restrict__ A, const float* __restrict__ B,
        float* __restrict__ C, int M, int N, int K,
        const int* __restrict__ rowidx, const int* __restrict__ cntp,
        const float* __restrict__ bias, const float* __restrict__ addp,
        const float* __restrict__ gatep)
{
    int Meff = cntp ? *cntp : M;
    int bm = blockIdx.y, bn = blockIdx.x;
    if (bm * 128 >= Meff) return;

    __shared__ unsigned As[2][16][TLD];
    __shared__ unsigned Bs[2][16][TLD];

    int tid  = threadIdx.x;
    int warp = tid >> 5, lane = tid & 31;
    int wm = (warp >> 2) * 64;   // warp m-offset: 0 or 64
    int wn = (warp & 3) * 32;    // warp n-offset: 0..96
    int lr = lane >> 2, lc = lane & 3;

    float acc[4][4][4];
    #pragma unroll
    for (int a = 0; a < 4; a++)
        #pragma unroll
        for (int b = 0; b < 4; b++)
            #pragma unroll
            for (int i = 0; i < 4; i++) acc[a][b][i] = 0.f;

    // A loads: 128 rows x 16 cols; row = tid/2, col half = (tid&1)*8
    int arow = tid >> 1, acol = (tid & 1) * 8;
    int gm = bm * 128 + arow;
    bool aok = gm < Meff;
    const float* Arow = A + (size_t)(aok ? (GATHER ? rowidx[gm] : gm) : 0) * K;

    // B loads: 16 rows x 128 cols; rows tid/32 and tid/32+8, col = (tid&31)*4
    int brow = tid >> 5;
    int bcol = (tid & 31) * 4;
    int gn = bn * 128 + bcol;

    float4 av0, av1, bv0, bv1;

    auto loadAB = [&](int k0){
        if (aok){
            av0 = *(const float4*)(Arow + k0 + acol);
            av1 = *(const float4*)(Arow + k0 + acol + 4);
        } else {
            av0 = av1 = make_float4(0.f,0.f,0.f,0.f);
        }
        if (gn + 3 < N){
            bv0 = *(const float4*)(B + (size_t)(k0 + brow) * N + gn);
            bv1 = *(const float4*)(B + (size_t)(k0 + brow + 8) * N + gn);
        } else {
            const float* r0 = B + (size_t)(k0 + brow) * N;
            const float* r1 = B + (size_t)(k0 + brow + 8) * N;
            bv0.x = (gn+0 < N) ? r0[gn+0] : 0.f;
            bv0.y = (gn+1 < N) ? r0[gn+1] : 0.f;
            bv0.z = (gn+2 < N) ? r0[gn+2] : 0.f;
            bv0.w = (gn+3 < N) ? r0[gn+3] : 0.f;
            bv1.x = (gn+0 < N) ? r1[gn+0] : 0.f;
            bv1.y = (gn+1 < N) ? r1[gn+1] : 0.f;
            bv1.z = (gn+2 < N) ? r1[gn+2] : 0.f;
            bv1.w = (gn+3 < N) ? r1[gn+3] : 0.f;
        }
    };

    auto storeAB = [&](int s){
        As[s][acol+0][arow] = f2tf(av0.x);
        As[s][acol+1][arow] = f2tf(av0.y);
        As[s][acol+2][arow] = f2tf(av0.z);
        As[s][acol+3][arow] = f2tf(av0.w);
        As[s][acol+4][arow] = f2tf(av1.x);
        As[s][acol+5][arow] = f2tf(av1.y);
        As[s][acol+6][arow] = f2tf(av1.z);
        As[s][acol+7][arow] = f2tf(av1.w);
        uint4 p0 = make_uint4(f2tf(bv0.x), f2tf(bv0.y), f2tf(bv0.z), f2tf(bv0.w));
        uint4 p1 = make_uint4(f2tf(bv1.x), f2tf(bv1.y), f2tf(bv1.z), f2tf(bv1.w));
        *(uint4*)&Bs[s][brow  ][bcol] = p0;
        *(uint4*)&Bs[s][brow+8][bcol] = p1;
    };

    loadAB(0);
    storeAB(0);
    __syncthreads();

    int buf = 0;
    for (int k0 = 0; k0 < K; k0 += 16){
        bool more = (k0 + 16) < K;
        if (more) loadAB(k0 + 16);

        #pragma unroll
        for (int kk = 0; kk < 16; kk += 8){
            unsigned af[4][4], bf[4][2];
            #pragma unroll
            for (int mt = 0; mt < 4; mt++){
                int r0 = wm + mt * 16 + lr;
                af[mt][0] = As[buf][kk + lc    ][r0    ];
                af[mt][1] = As[buf][kk + lc    ][r0 + 8];
                af[mt][2] = As[buf][kk + lc + 4][r0    ];
                af[mt][3] = As[buf][kk + lc + 4][r0 + 8];
            }
            #pragma unroll
            for (int nt = 0; nt < 4; nt++){
                int c0 = wn + nt * 8 + lr;
                bf[nt][0] = Bs[buf][kk + lc    ][c0];
                bf[nt][1] = Bs[buf][kk + lc + 4][c0];
            }
            #pragma unroll
            for (int mt = 0; mt < 4; mt++)
                #pragma unroll
                for (int nt = 0; nt < 4; nt++)
                    mma_tf32(acc[mt][nt], af[mt][0], af[mt][1], af[mt][2], af[mt][3],
                             bf[nt][0], bf[nt][1]);
        }

        if (more){
            storeAB(buf ^ 1);
            __syncthreads();
            buf ^= 1;
        }
    }

    // epilogue: c[i] at (row + (i>=2)*8, col + (i&1))
    #pragma unroll
    for (int mt = 0; mt < 4; mt++){
        #pragma unroll
        for (int nt = 0; nt < 4; nt++){
            int r0 = bm * 128 + wm + mt * 16 + lr;
            int c0 = bn * 128 + wn + nt * 8 + 2 * lc;
            #pragma unroll
            for (int i = 0; i < 4; i++){
                int row = r0 + ((i >> 1) * 8);
                int col = c0 + (i & 1);
                if (row < Meff && col < N){
                    float v = acc[mt][nt][i];
                    if (EPI == 0){
                        C[(size_t)row * N + col] = v;
                    } else if (EPI == 1){
                        C[(size_t)row * N + col] = v + addp[(size_t)row * N + col];
                    } else if (EPI == 2){
                        v += bias[col];
                        C[(size_t)row * N + col] = 0.5f * v * (1.0f + erff(v * 0.7071067811865475f));
                    } else {
                        int tok = rowidx[row];
                        atomicAdd(&C[(size_t)tok * N + col], gatep[row] * (v + bias[col]));
                    }
                }
            }
        }
    }
}

// ---------------- RoPE on q (in place, cols [DN,DN+64) of each head) ----------------
__global__ void ropeq_kernel(float* __restrict__ q){
    int s = blockIdx.x, h = blockIdx.y, j = threadIdx.x; // 64 threads
    float* base = q + (size_t)s * (NH*QD) + h * QD + DN;
    __shared__ float xs[64];
    xs[j] = base[j];
    __syncthreads();
    int m = j & 31;
    float freq = (float)(1.0 / pow(10000.0, (double)m / 32.0));
    float ang = (float)s * freq;
    float sn, cs; sincosf(ang, &sn, &cs);
    float other = (j < 32) ? -xs[j + 32] : xs[j - 32];
    base[j] = xs[j] * cs + other * sn;
}

// ---------------- build k_full [S, H*192]: nope from kv, roped k_rope broadcast ----------------
__global__ void buildkf_kernel(const float* __restrict__ kv, const float* __restrict__ ckv,
                               float* __restrict__ kf){
    int s = blockIdx.x, t = threadIdx.x; // 256
    __shared__ float raw[64], kr[64];
    if (t < 64) raw[t] = ckv[(size_t)s * (RDIM + DRp) + RDIM + t];
    __syncthreads();
    if (t < 64){
        int m = t & 31;
        float freq = (float)(1.0 / pow(10000.0, (double)m / 32.0));
        float ang = (float)s * freq;
        float sn, cs; sincosf(ang, &sn, &cs);
        float other = (t < 32) ? -raw[t + 32] : raw[t - 32];
        kr[t] = raw[t] * cs + other * sn;
    }
    __syncthreads();
    for (int idx = t; idx < NH * QD; idx += 256){
        int h = idx / QD, j = idx - h * QD;
        kf[(size_t)s * (NH*QD) + idx] = (j < DN) ? kv[(size_t)s * (NH*KVD) + h*KVD + j]
                                                 : kr[j - DN];
    }
}

// ---------------- indexer scores ----------------
__global__ void idx_kernel(const float* __restrict__ qi, const float* __restrict__ ki,
                           const float* __restrict__ wt, float* __restrict__ outI){
    int qb = blockIdx.y * 16, kb = blockIdx.x * 16;
    __shared__ float sq[16][HIi*DIi];
    __shared__ float sk[16][DIi + 1];
    __shared__ float sw[16][HIi];
    int t = threadIdx.x; // 256
    for (int i = t; i < 16 * HIi * DIi; i += 256)
        sq[i >> 8][i & 255] = qi[(size_t)(qb + (i >> 8)) * (HIi*DIi) + (i & 255)];
    for (int i = t; i < 16 * DIi; i += 256)
        sk[i >> 6][i & 63] = ki[(size_t)(kb + (i >> 6)) * DIi + (i & 63)];
    if (t < 16 * HIi) sw[t >> 2][t & 3] = wt[(size_t)(qb + (t >> 2)) * HIi + (t & 3)];
    __syncthreads();
    int tq = t >> 4, tk = t & 15;
    int gq = qb + tq, gk = kb + tk;
    float res;
    if (gk > gq){
        res = -FLT_MAX;
    } else {
        res = 0.f;
        #pragma unroll
        for (int hh = 0; hh < HIi; hh++){
            float dot = 0.f;
            #pragma unroll
            for (int d = 0; d < DIi; d++) dot = fmaf(sq[tq][hh*DIi + d], sk[tk][d], dot);
            res += fmaxf(dot, 0.f) * sw[tq][hh];
        }
    }
    outI[(size_t)gq * SS + gk] = res;
}

// ---------------- per-row top-k (radix select + ascending-index tie-break) ----------------
__device__ __forceinline__ int blockScanInc(int v, int* scan, int t){
    __syncthreads();
    scan[t] = v; __syncthreads();
    for (int off = 1; off < 256; off <<= 1){
        int x = (t >= off) ? scan[t - off] : 0;
        __syncthreads();
        scan[t] += x;
        __syncthreads();
    }
    return scan[t];
}

__global__ void topk_kernel(const float* __restrict__ idxs, int* __restrict__ sel,
                            int* __restrict__ nsel){
    int q = blockIdx.x, t = threadIdx.x; // 256 threads
    int n = q + 1;
    if (n <= KTOPk){
        for (int k = t; k < n; k += 256) sel[(size_t)q * KTOPk + k] = k;
        if (t == 0) nsel[q] = n;
        return;
    }
    __shared__ unsigned su[SS];
    const float* row = idxs + (size_t)q * SS;
    for (int k = t; k < n; k += 256){
        unsigned b = __float_as_uint(row[k]);
        su[k] = (b & 0x80000000u) ? ~b : (b | 0x80000000u);
    }
    __syncthreads();

    __shared__ int hist[256];
    __shared__ int sdig, srem;
    unsigned prefix = 0, mask = 0;
    int remaining = KTOPk;
    for (int pass = 0; pass < 4; pass++){
        int shift = 24 - pass * 8;
        hist[t] = 0;
        __syncthreads();
        for (int k = t; k < n; k += 256){
            unsigned u = su[k];
            if ((u & mask) == prefix) atomicAdd(&hist[(u >> shift) & 255], 1);
        }
        __syncthreads();
        if (t == 0){
            int rem = remaining, d;
            for (d = 255; d > 0; d--){
                if (hist[d] >= rem) break;
                rem -= hist[d];
            }
            sdig = d; srem = rem;
        }
        __syncthreads();
        prefix |= ((unsigned)sdig) << shift;
        mask   |= (255u << shift);
        remaining = srem;
        __syncthreads();
    }
    unsigned uthr = prefix;
    int T = remaining;

    __shared__ int scan[256];
    __shared__ int base_eq, base_sel;
    if (t == 0){ base_eq = 0; base_sel = 0; }
    __syncthreads();
    for (int c0 = 0; c0 < n; c0 += 256){
        int k = c0 + t;
        unsigned u = (k < n) ? su[k] : 0u;
        int is_gt = (k < n) && (u > uthr);
        int is_eq = (k < n) && (u == uthr);
        int eq_inc = blockScanInc(is_eq, scan, t);
        int tie_rank = base_eq + (eq_inc - is_eq);
        int chunk_eq = scan[255];
        __syncthreads();
        int is_sel = is_gt || (is_eq && tie_rank < T);
        int sel_inc = blockScanInc(is_sel, scan, t);
        int pos = base_sel + (sel_inc - is_sel);
        int chunk_sel = scan[255];
        if (is_sel) sel[(size_t)q * KTOPk + pos] = k;
        __syncthreads();
        if (t == 0){ base_eq += chunk_eq; base_sel += chunk_sel; }
        __syncthreads();
    }
    if (t == 0) nsel[q] = KTOPk;
}

// ---------------- sparse attention over selected keys ----------------
__global__ void __launch_bounds__(128)
attn_kernel(const float* __restrict__ qf, const float* __restrict__ kf,
            const float* __restrict__ kv, const int* __restrict__ sel,
            const int* __restrict__ nsel, float* __restrict__ o){
    int s = blockIdx.x, h = blockIdx.y;
    int t = threadIdx.x;            // 128
    int w = t >> 5, lane = t & 31;
    int ns = nsel[s];

    __shared__ float qs[QD];
    __shared__ float lg[KTOPk];
    __shared__ int   ksm[KTOPk];
    __shared__ float red[4];

    for (int i = t; i < QD; i += 128) qs[i] = qf[(size_t)s * (NH*QD) + h * QD + i];
    for (int i = t; i < ns; i += 128) ksm[i] = sel[(size_t)s * KTOPk + i];
    __syncthreads();

    const float scale = 0.07216878364870323f; // 1/sqrt(192)
    for (int j = w; j < ns; j += 4){
        const float* kp = kf + (size_t)ksm[j] * (NH*QD) + h * QD;
        float d = 0.f;
        #pragma unroll
        for (int e = 0; e < 6; e++) d = fmaf(qs[lane + e*32], kp[lane + e*32], d);
        #pragma unroll
        for (int off = 16; off; off >>= 1) d += __shfl_xor_sync(0xffffffffu, d, off);
        if (lane == 0) lg[j] = d * scale;
    }
    __syncthreads();

    float m = -FLT_MAX;
    for (int i = t; i < ns; i += 128) m = fmaxf(m, lg[i]);
    #pragma unroll
    for (int off = 16; off; off >>= 1) m = fmaxf(m, __shfl_xor_sync(0xffffffffu, m, off));
    if (lane == 0) red[w] = m;
    __syncthreads();
    m = fmaxf(fmaxf(red[0], red[1]), fmaxf(red[2], red[3]));
    __syncthreads();

    float psum = 0.f;
    for (int i = t; i < ns; i += 128){
        float p = expf(lg[i] - m);
        lg[i] = p;
        psum += p;
    }
    #pragma unroll
    for (int off = 16; off; off >>= 1) psum += __shfl_xor_sync(0xffffffffu, psum, off);
    if (lane == 0) red[w] = psum;
    __syncthreads();
    float tot = red[0] + red[1] + red[2] + red[3];
    float inv = 1.f / tot;

    const float* vb = kv + h * KVD + DN;
    float a0 = 0.f, a1 = 0.f, a2 = 0.f, a3 = 0.f;
    int j = 0;
    for (; j + 3 < ns; j += 4){
        a0 = fmaf(lg[j+0], vb[(size_t)ksm[j+0] * (NH*KVD) + t], a0);
        a1 = fmaf(lg[j+1], vb[(size_t)ksm[j+1] * (NH*KVD) + t], a1);
        a2 = fmaf(lg[j+2], vb[(size_t)ksm[j+2] * (NH*KVD) + t], a2);
        a3 = fmaf(lg[j+3], vb[(size_t)ksm[j+3] * (NH*KVD) + t], a3);
    }
    for (; j < ns; j++) a0 = fmaf(lg[j], vb[(size_t)ksm[j] * (NH*KVD) + t], a0);
    o[(size_t)s * (NH*DVp) + h * DVp + t] = ((a0 + a1) + (a2 + a3)) * inv;
}

// ---------------- MoE gating ----------------
__global__ void zero_kernel(int* cnt, float* ps){
    if (threadIdx.x < NE){ cnt[threadIdx.x] = 0; ps[threadIdx.x] = 0.f; }
}

__global__ void gate_kernel(const float* __restrict__ rl, int* __restrict__ cnt,
                            float* __restrict__ ps, int* __restrict__ list,
                            float* __restrict__ gate){
    int tk = blockIdx.x * 256 + threadIdx.x;
    if (tk >= SS) return;
    float l[NE], p[NE];
    float mx = -FLT_MAX;
    #pragma unroll
    for (int e = 0; e < NE; e++){ l[e] = rl[(size_t)tk * NE + e]; mx = fmaxf(mx, l[e]); }
    float sum = 0.f;
    #pragma unroll
    for (int e = 0; e < NE; e++){ p[e] = expf(l[e] - mx); sum += p[e]; }
    #pragma unroll
    for (int e = 0; e < NE; e++) p[e] /= sum;
    int i0 = 0;
    #pragma unroll
    for (int e = 1; e < NE; e++) if (p[e] > p[i0]) i0 = e;
    int i1 = -1;
    #pragma unroll
    for (int e = 0; e < NE; e++) if (e != i0 && (i1 < 0 || p[e] > p[i1])) i1 = e;
    float g0 = p[i0], g1 = p[i1], gs = g0 + g1;
    int pos0 = atomicAdd(&cnt[i0], 1);
    list[i0 * SS + pos0] = tk; gate[i0 * SS + pos0] = g0 / gs;
    int pos1 = atomicAdd(&cnt[i1], 1);
    list[i1 * SS + pos1] = tk; gate[i1 * SS + pos1] = g1 / gs;
    #pragma unroll
    for (int e = 0; e < NE; e++) atomicAdd(&ps[e], p[e]);
}

__global__ void aux_kernel(const int* __restrict__ cnt, const float* __restrict__ ps,
                           float* __restrict__ outAux){
    float a = 0.f;
    for (int e = 0; e < NE; e++)
        a += ((float)cnt[e] / (float)SS) * (ps[e] / (float)SS);
    *outAux = (float)NE * a;
}

// ---------------- host ----------------
extern "C" void kernel_launch(void* const* d_in, const int* in_sizes, int n_in,
                              void* d_out, int out_size){
    const float* x    = (const float*)d_in[0];
    const float* n1w  = (const float*)d_in[1];
    const float* n2w  = (const float*)d_in[2];
    const float* kvnw = (const float*)d_in[3];
    const float* Wq   = (const float*)d_in[4];
    const float* Wkva = (const float*)d_in[5];
    const float* Wkvb = (const float*)d_in[6];
    const float* Wo   = (const float*)d_in[7];
    const float* Wiq  = (const float*)d_in[8];
    const float* Wik  = (const float*)d_in[9];
    const float* Wiw  = (const float*)d_in[10];
    const float* Wr   = (const float*)d_in[11];
    const float* W1   = (const float*)d_in[12];
    const float* b1   = (const float*)d_in[13];
    const float* W2   = (const float*)d_in[14];
    const float* b2   = (const float*)d_in[15];

    float* out     = (float*)d_out;
    float* out_x   = out;
    float* out_aux = out + (size_t)SS * DD;
    float* out_idx = out + (size_t)SS * DD + 1;

    float *ph, *pq, *pckv, *pc, *pkv, *pkf, *pqi, *pki, *pwt, *po, *px2, *ph2, *prl, *phid, *pgate, *pps;
    int *psel, *pnsel, *pcnt, *plist;
    cudaGetSymbolAddress((void**)&ph,   g_h);
    cudaGetSymbolAddress((void**)&pq,   g_q);
    cudaGetSymbolAddress((void**)&pckv, g_ckv);
    cudaGetSymbolAddress((void**)&pc,   g_c);
    cudaGetSymbolAddress((void**)&pkv,  g_kv);
    cudaGetSymbolAddress((void**)&pkf,  g_kf);
    cudaGetSymbolAddress((void**)&pqi,  g_qi);
    cudaGetSymbolAddress((void**)&pki,  g_ki);
    cudaGetSymbolAddress((void**)&pwt,  g_wt);
    cudaGetSymbolAddress((void**)&po,   g_o);
    cudaGetSymbolAddress((void**)&px2,  g_x2);
    cudaGetSymbolAddress((void**)&ph2,  g_h2);
    cudaGetSymbolAddress((void**)&prl,  g_rl);
    cudaGetSymbolAddress((void**)&phid, g_hid);
    cudaGetSymbolAddress((void**)&pgate,g_gate);
    cudaGetSymbolAddress((void**)&pps,  g_ps);
    cudaGetSymbolAddress((void**)&psel, g_sel);
    cudaGetSymbolAddress((void**)&pnsel,g_nsel);
    cudaGetSymbolAddress((void**)&pcnt, g_cnt);
    cudaGetSymbolAddress((void**)&plist,g_list);

    // 1. h = rms(x, norm1_w)
    rms_kernel<<<SS, 256>>>(x, DD, DD, n1w, ph, DD);
    // 2. q = h @ Wq  (tf32)
    tgemm_k<0,false><<<dim3(24,16), 256>>>(ph, Wq, pq, SS, NH*QD, DD, nullptr,nullptr,nullptr,nullptr,nullptr);
    // 3. ckv = h @ Wkva  (tf32)
    tgemm_k<0,false><<<dim3(5,16), 256>>>(ph, Wkva, pckv, SS, RDIM+DRp, DD, nullptr,nullptr,nullptr,nullptr,nullptr);
    // 4. c = rms(ckv[:, :R], kv_norm_w)
    rms_kernel<<<SS, 256>>>(pckv, RDIM+DRp, RDIM, kvnw, pc, RDIM);
    // 5. kv = c @ Wkvb  (tf32)
    tgemm_k<0,false><<<dim3(32,16), 256>>>(pc, Wkvb, pkv, SS, NH*KVD, RDIM, nullptr,nullptr,nullptr,nullptr,nullptr);
    // 6. rope on q (in place)
    ropeq_kernel<<<dim3(SS, NH), 64>>>(pq);
    // 7. k_full
    buildkf_kernel<<<SS, 256>>>(pkv, pckv, pkf);
    // 8. indexer projections (fp32 — keep top-k selection bit-identical)
    sgemm_k<0,false><<<dim3(2,16), 256>>>(ph, Wiq, pqi, SS, HIi*DIi, DD, nullptr,nullptr,nullptr,nullptr,nullptr);
    sgemm_k<0,false><<<dim3(1,16), 256>>>(ph, Wik, pki, SS, DIi, DD, nullptr,nullptr,nullptr,nullptr,nullptr);
    sgemm_k<0,false><<<dim3(1,16), 256>>>(ph, Wiw, pwt, SS, HIi, DD, nullptr,nullptr,nullptr,nullptr,nullptr);
    // 9. idx_scores (written straight into output)
    idx_kernel<<<dim3(128,128), 256>>>(pqi, pki, pwt, out_idx);
    // 10. per-row top-k selection
    topk_kernel<<<SS, 256>>>(out_idx, psel, pnsel);
    // 11. sparse attention
    attn_kernel<<<dim3(SS, NH), 128>>>(pq, pkf, pkv, psel, pnsel, po);
    // 12. x2 = x + o @ Wo  (tf32)
    tgemm_k<1,false><<<dim3(16,16), 256>>>(po, Wo, px2, SS, DD, NH*DVp, nullptr,nullptr,nullptr, x, nullptr);
    // 13. h2 = rms(x2, norm2_w)
    rms_kernel<<<SS, 256>>>(px2, DD, DD, n2w, ph2, DD);
    // 14. router logits (fp32 — keep expert selection bit-identical)
    sgemm_k<0,false><<<dim3(1,16), 256>>>(ph2, Wr, prl, SS, NE, DD, nullptr,nullptr,nullptr,nullptr,nullptr);
    // 15. gating
    zero_kernel<<<1, 32>>>(pcnt, pps);
    gate_kernel<<<(SS+255)/256, 256>>>(prl, pcnt, pps, plist, pgate);
    aux_kernel<<<1, 1>>>(pcnt, pps, out_aux);
    // 16. init output x region with x2, then scatter-add MoE  (tf32)
    cudaMemcpyAsync(out_x, px2, sizeof(float)*(size_t)SS*DD, cudaMemcpyDeviceToDevice, 0);
    for (int e = 0; e < NE; e++){
        // hid = gelu(gather(h2) @ W1[e] + b1[e])
        tgemm_k<2,true><<<dim3(64,16), 256>>>(ph2, W1 + (size_t)e*DD*DFF, phid,
                                              SS, DFF, DD,
                                              plist + e*SS, pcnt + e,
                                              b1 + (size_t)e*DFF, nullptr, nullptr);
        // out[tok] += gate * (hid @ W2[e] + b2[e])
        tgemm_k<3,false><<<dim3(16,16), 256>>>(phid, W2 + (size_t)e*DFF*DD, out_x,
                                               SS, DD, DFF,
                                               plist + e*SS, pcnt + e,
                                               b2 + (size_t)e*DD, nullptr, pgate + e*SS);
    }
}

// round 15
// speedup vs baseline: 1.0049x; 1.0017x over previous
#include <cuda_runtime.h>
#include <math.h>
#include <float.h>

#define SS 2048
#define DD 2048
#define NH 16
#define DN 128
#define DRp 64
#define DVp 128
#define RDIM 512
#define HIi 4
#define DIi 64
#define KTOPk 512
#define NE 4
#define DFF 8192
#define QD 192   /* DN+DR */
#define KVD 256  /* DN+DV */

// ---------------- scratch (device globals; no allocation allowed) ----------------
__device__ float g_h  [(size_t)SS*DD];
__device__ float g_q  [(size_t)SS*NH*QD];
__device__ float g_ckv[(size_t)SS*(RDIM+DRp)];
__device__ float g_c  [(size_t)SS*RDIM];
__device__ float g_kv [(size_t)SS*NH*KVD];
__device__ float g_kf [(size_t)SS*NH*QD];
__device__ float g_qi [(size_t)SS*HIi*DIi];
__device__ float g_ki [(size_t)SS*DIi];
__device__ float g_wt [(size_t)SS*HIi];
__device__ float g_o  [(size_t)SS*NH*DVp];
__device__ float g_x2 [(size_t)SS*DD];
__device__ float g_h2 [(size_t)SS*DD];
__device__ float g_rl [(size_t)SS*NE];
__device__ float g_hid[(size_t)SS*DFF];
__device__ int   g_sel[(size_t)SS*KTOPk];
__device__ int   g_nsel[SS];
__device__ int   g_cnt[NE];
__device__ float g_ps [NE];
__device__ int   g_list[NE*SS];
__device__ float g_gate[NE*SS];

// ---------------- RMSNorm ----------------
__global__ void rms_kernel(const float* __restrict__ in, int istride, int width,
                           const float* __restrict__ w, float* __restrict__ out, int ostride){
    int row = blockIdx.x;
    const float* ip = in + (size_t)row * istride;
    float ssq = 0.f;
    for (int i = threadIdx.x; i < width; i += blockDim.x){ float v = ip[i]; ssq += v*v; }
    __shared__ float red[32];
    int lane = threadIdx.x & 31, wid = threadIdx.x >> 5;
    #pragma unroll
    for (int o = 16; o; o >>= 1) ssq += __shfl_xor_sync(0xffffffffu, ssq, o);
    if (lane == 0) red[wid] = ssq;
    __syncthreads();
    if (threadIdx.x == 0){
        float tot = 0.f; int nw = blockDim.x >> 5;
        for (int i = 0; i < nw; i++) tot += red[i];
        red[0] = rsqrtf(tot / (float)width + 1e-6f);
    }
    __syncthreads();
    float sc = red[0];
    float* op = out + (size_t)row * ostride;
    for (int i = threadIdx.x; i < width; i += blockDim.x) op[i] = ip[i] * sc * w[i];
}

// ---------------- legacy fp32 SGEMM (kept for small indexer/router GEMMs) ----------------
template<int EPI, bool GATHER>
__global__ void __launch_bounds__(256)
sgemm_k(const float* __restrict__ A, const float* __restrict__ B,
        float* __restrict__ C, int M, int N, int K,
        const int* __restrict__ rowidx, const int* __restrict__ cntp,
        const float* __restrict__ bias, const float* __restrict__ addp,
        const float* __restrict__ gatep)
{
    int Meff = cntp ? *cntp : M;
    int bm = blockIdx.y, bn = blockIdx.x;
    if (bm * 128 >= Meff) return;

    __shared__ float As[8][128];
    __shared__ float Bs[8][128];

    int tid = threadIdx.x;
    int tx = tid & 15, ty = tid >> 4;

    float acc[8][8];
    #pragma unroll
    for (int i = 0; i < 8; i++)
        #pragma unroll
        for (int j = 0; j < 8; j++) acc[i][j] = 0.f;

    int arow = tid >> 1, acol = (tid & 1) * 4;
    int gm = bm * 128 + arow;
    bool aok = gm < Meff;
    int asrc = aok ? (GATHER ? rowidx[gm] : gm) : 0;
    const float* Arow = A + (size_t)asrc * K;

    int brow = tid >> 5, bcol = (tid & 31) * 4;
    int gn = bn * 128 + bcol;

    for (int k0 = 0; k0 < K; k0 += 8){
        float4 av = make_float4(0.f,0.f,0.f,0.f);
        if (aok) av = *(const float4*)(Arow + k0 + acol);
        float4 bv;
        if (gn + 3 < N){
            bv = *(const float4*)(B + (size_t)(k0 + brow) * N + gn);
        } else {
            float t0 = (gn+0 < N) ? B[(size_t)(k0+brow)*N + gn+0] : 0.f;
            float t1 = (gn+1 < N) ? B[(size_t)(k0+brow)*N + gn+1] : 0.f;
            float t2 = (gn+2 < N) ? B[(size_t)(k0+brow)*N + gn+2] : 0.f;
            float t3 = (gn+3 < N) ? B[(size_t)(k0+brow)*N + gn+3] : 0.f;
            bv = make_float4(t0,t1,t2,t3);
        }
        __syncthreads();
        As[acol+0][arow] = av.x; As[acol+1][arow] = av.y;
        As[acol+2][arow] = av.z; As[acol+3][arow] = av.w;
        *(float4*)(&Bs[brow][bcol]) = bv;
        __syncthreads();

        #pragma unroll
        for (int kk = 0; kk < 8; kk++){
            float4 a0 = *(const float4*)(&As[kk][ty*8]);
            float4 a1 = *(const float4*)(&As[kk][ty*8+4]);
            float4 b0 = *(const float4*)(&Bs[kk][tx*8]);
            float4 b1 = *(const float4*)(&Bs[kk][tx*8+4]);
            float a[8] = {a0.x,a0.y,a0.z,a0.w,a1.x,a1.y,a1.z,a1.w};
            float b[8] = {b0.x,b0.y,b0.z,b0.w,b1.x,b1.y,b1.z,b1.w};
            #pragma unroll
            for (int i = 0; i < 8; i++)
                #pragma unroll
                for (int j = 0; j < 8; j++)
                    acc[i][j] = fmaf(a[i], b[j], acc[i][j]);
        }
    }

    int cm = bm * 128 + ty * 8, cn = bn * 128 + tx * 8;
    #pragma unroll
    for (int i = 0; i < 8; i++){
        int row = cm + i;
        if (row >= Meff) break;
        #pragma unroll
        for (int j = 0; j < 8; j++){
            int col = cn + j;
            if (col >= N) break;
            float v = acc[i][j];
            if (EPI == 0){
                C[(size_t)row * N + col] = v;
            } else if (EPI == 1){
                C[(size_t)row * N + col] = v + addp[(size_t)row * N + col];
            } else if (EPI == 2){
                v += bias[col];
                C[(size_t)row * N + col] = 0.5f * v * (1.0f + erff(v * 0.7071067811865475f));
            } else {
                int tok = rowidx[row];
                atomicAdd(&C[(size_t)tok * N + col], gatep[row] * (v + bias[col]));
            }
        }
    }
}

// ---------------- tf32 tensor-core GEMM: 128x128x16 tile, double-buffered ----------------
__device__ __forceinline__ unsigned f2tf(float x){
    unsigned u; asm("cvt.rna.tf32.f32 %0, %1;" : "=r"(u) : "f"(x)); return u;
}

__device__ __forceinline__ void mma_tf32(float* c,
    unsigned a0, unsigned a1, unsigned a2, unsigned a3, unsigned b0, unsigned b1){
    asm volatile(
        "mma.sync.aligned.m16n8k8.row.col.f32.tf32.tf32.f32 "
        "{%0,%1,%2,%3},{%4,%5,%6,%7},{%8,%9},{%0,%1,%2,%3};"
        : "+f"(c[0]), "+f"(c[1]), "+f"(c[2]), "+f"(c[3])
        : "r"(a0), "r"(a1), "r"(a2), "r"(a3), "r"(b0), "r"(b1));
}

#define TLD 136  /* padded stride: bank = (8*kc + r) % 32 hits all banks */

template<int EPI, bool GATHER>
__global__ void __launch_bounds__(256)
tgemm_k(const float* __restrict__ A, const float* __restrict__ B,
        float* __restrict__ C, int M, int N, int K,
        const int* __restrict__ rowidx, const int* __restrict__ cntp,
        const float* __restrict__ bias, const float* __restrict__ addp,
        const float* __restrict__ gatep)
{
    int Meff = cntp ? *cntp : M;
    int bm = blockIdx.y, bn = blockIdx.x;
    if (bm * 128 >= Meff) return;

    __shared__ unsigned As[2][16][TLD];
    __shared__ unsigned Bs[2][16][TLD];

    int tid  = threadIdx.x;
    int warp = tid >> 5, lane = tid & 31;
    int wm = (warp >> 2) * 64;   // warp m-offset: 0 or 64
    int wn = (warp & 3) * 32;    // warp n-offset: 0..96
    int lr = lane >> 2, lc = lane & 3;

    float acc[4][4][4];
    #pragma unroll
    for (int a = 0; a < 4; a++)
        #pragma unroll
        for (int b = 0; b < 4; b++)
            #pragma unroll
            for (int i = 0; i < 4; i++) acc[a][b][i] = 0.f;

    // A loads: 128 rows x 16 cols; row = tid/2, col half = (tid&1)*8
    int arow = tid >> 1, acol = (tid & 1) * 8;
    int gm = bm * 128 + arow;
    bool aok = gm < Meff;
    const float* Arow = A + (size_t)(aok ? (GATHER ? rowidx[gm] : gm) : 0) * K;

    // B loads: 16 rows x 128 cols; rows tid/32 and tid/32+8, col = (tid&31)*4
    int brow = tid >> 5;
    int bcol = (tid & 31) * 4;
    int gn = bn * 128 + bcol;

    float4 av0, av1, bv0, bv1;

    auto loadAB = [&](int k0){
        if (aok){
            av0 = *(const float4*)(Arow + k0 + acol);
            av1 = *(const float4*)(Arow + k0 + acol + 4);
        } else {
            av0 = av1 = make_float4(0.f,0.f,0.f,0.f);
        }
        if (gn + 3 < N){
            bv0 = *(const float4*)(B + (size_t)(k0 + brow) * N + gn);
            bv1 = *(const float4*)(B + (size_t)(k0 + brow + 8) * N + gn);
        } else {
            const float* r0 = B + (size_t)(k0 + brow) * N;
            const float* r1 = B + (size_t)(k0 + brow + 8) * N;
            bv0.x = (gn+0 < N) ? r0[gn+0] : 0.f;
            bv0.y = (gn+1 < N) ? r0[gn+1] : 0.f;
            bv0.z = (gn+2 < N) ? r0[gn+2] : 0.f;
            bv0.w = (gn+3 < N) ? r0[gn+3] : 0.f;
            bv1.x = (gn+0 < N) ? r1[gn+0] : 0.f;
            bv1.y = (gn+1 < N) ? r1[gn+1] : 0.f;
            bv1.z = (gn+2 < N) ? r1[gn+2] : 0.f;
            bv1.w = (gn+3 < N) ? r1[gn+3] : 0.f;
        }
    };

    auto storeAB = [&](int s){
        As[s][acol+0][arow] = f2tf(av0.x);
        As[s][acol+1][arow] = f2tf(av0.y);
        As[s][acol+2][arow] = f2tf(av0.z);
        As[s][acol+3][arow] = f2tf(av0.w);
        As[s][acol+4][arow] = f2tf(av1.x);
        As[s][acol+5][arow] = f2tf(av1.y);
        As[s][acol+6][arow] = f2tf(av1.z);
        As[s][acol+7][arow] = f2tf(av1.w);
        uint4 p0 = make_uint4(f2tf(bv0.x), f2tf(bv0.y), f2tf(bv0.z), f2tf(bv0.w));
        uint4 p1 = make_uint4(f2tf(bv1.x), f2tf(bv1.y), f2tf(bv1.z), f2tf(bv1.w));
        *(uint4*)&Bs[s][brow  ][bcol] = p0;
        *(uint4*)&Bs[s][brow+8][bcol] = p1;
    };

    loadAB(0);
    storeAB(0);
    __syncthreads();

    int buf = 0;
    for (int k0 = 0; k0 < K; k0 += 16){
        bool more = (k0 + 16) < K;
        if (more) loadAB(k0 + 16);

        #pragma unroll
        for (int kk = 0; kk < 16; kk += 8){
            unsigned af[4][4], bf[4][2];
            #pragma unroll
            for (int mt = 0; mt < 4; mt++){
                int r0 = wm + mt * 16 + lr;
                af[mt][0] = As[buf][kk + lc    ][r0    ];
                af[mt][1] = As[buf][kk + lc    ][r0 + 8];
                af[mt][2] = As[buf][kk + lc + 4][r0    ];
                af[mt][3] = As[buf][kk + lc + 4][r0 + 8];
            }
            #pragma unroll
            for (int nt = 0; nt < 4; nt++){
                int c0 = wn + nt * 8 + lr;
                bf[nt][0] = Bs[buf][kk + lc    ][c0];
                bf[nt][1] = Bs[buf][kk + lc + 4][c0];
            }
            #pragma unroll
            for (int mt = 0; mt < 4; mt++)
                #pragma unroll
                for (int nt = 0; nt < 4; nt++)
                    mma_tf32(acc[mt][nt], af[mt][0], af[mt][1], af[mt][2], af[mt][3],
                             bf[nt][0], bf[nt][1]);
        }

        if (more){
            storeAB(buf ^ 1);
            __syncthreads();
            buf ^= 1;
        }
    }

    // epilogue: c[i] at (row + (i>=2)*8, col + (i&1))
    #pragma unroll
    for (int mt = 0; mt < 4; mt++){
        #pragma unroll
        for (int nt = 0; nt < 4; nt++){
            int r0 = bm * 128 + wm + mt * 16 + lr;
            int c0 = bn * 128 + wn + nt * 8 + 2 * lc;
            #pragma unroll
            for (int i = 0; i < 4; i++){
                int row = r0 + ((i >> 1) * 8);
                int col = c0 + (i & 1);
                if (row < Meff && col < N){
                    float v = acc[mt][nt][i];
                    if (EPI == 0){
                        C[(size_t)row * N + col] = v;
                    } else if (EPI == 1){
                        C[(size_t)row * N + col] = v + addp[(size_t)row * N + col];
                    } else if (EPI == 2){
                        v += bias[col];
                        C[(size_t)row * N + col] = 0.5f * v * (1.0f + erff(v * 0.7071067811865475f));
                    } else {
                        int tok = rowidx[row];
                        atomicAdd(&C[(size_t)tok * N + col], gatep[row] * (v + bias[col]));
                    }
                }
            }
        }
    }
}

// ---------------- RoPE on q (in place, cols [DN,DN+64) of each head) ----------------
__global__ void ropeq_kernel(float* __restrict__ q){
    int s = blockIdx.x, h = blockIdx.y, j = threadIdx.x; // 64 threads
    float* base = q + (size_t)s * (NH*QD) + h * QD + DN;
    __shared__ float xs[64];
    xs[j] = base[j];
    __syncthreads();
    int m = j & 31;
    float freq = (float)(1.0 / pow(10000.0, (double)m / 32.0));
    float ang = (float)s * freq;
    float sn, cs; sincosf(ang, &sn, &cs);
    float other = (j < 32) ? -xs[j + 32] : xs[j - 32];
    base[j] = xs[j] * cs + other * sn;
}

// ---------------- build k_full [S, H*192]: nope from kv, roped k_rope broadcast ----------------
__global__ void buildkf_kernel(const float* __restrict__ kv, const float* __restrict__ ckv,
                               float* __restrict__ kf){
    int s = blockIdx.x, t = threadIdx.x; // 256
    __shared__ float raw[64], kr[64];
    if (t < 64) raw[t] = ckv[(size_t)s * (RDIM + DRp) + RDIM + t];
    __syncthreads();
    if (t < 64){
        int m = t & 31;
        float freq = (float)(1.0 / pow(10000.0, (double)m / 32.0));
        float ang = (float)s * freq;
        float sn, cs; sincosf(ang, &sn, &cs);
        float other = (t < 32) ? -raw[t + 32] : raw[t - 32];
        kr[t] = raw[t] * cs + other * sn;
    }
    __syncthreads();
    for (int idx = t; idx < NH * QD; idx += 256){
        int h = idx / QD, j = idx - h * QD;
        kf[(size_t)s * (NH*QD) + idx] = (j < DN) ? kv[(size_t)s * (NH*KVD) + h*KVD + j]
                                                 : kr[j - DN];
    }
}

// ---------------- indexer scores ----------------
__global__ void idx_kernel(const float* __restrict__ qi, const float* __restrict__ ki,
                           const float* __restrict__ wt, float* __restrict__ outI){
    int qb = blockIdx.y * 16, kb = blockIdx.x * 16;
    __shared__ float sq[16][HIi*DIi];
    __shared__ float sk[16][DIi + 1];
    __shared__ float sw[16][HIi];
    int t = threadIdx.x; // 256
    for (int i = t; i < 16 * HIi * DIi; i += 256)
        sq[i >> 8][i & 255] = qi[(size_t)(qb + (i >> 8)) * (HIi*DIi) + (i & 255)];
    for (int i = t; i < 16 * DIi; i += 256)
        sk[i >> 6][i & 63] = ki[(size_t)(kb + (i >> 6)) * DIi + (i & 63)];
    if (t < 16 * HIi) sw[t >> 2][t & 3] = wt[(size_t)(qb + (t >> 2)) * HIi + (t & 3)];
    __syncthreads();
    int tq = t >> 4, tk = t & 15;
    int gq = qb + tq, gk = kb + tk;
    float res;
    if (gk > gq){
        res = -FLT_MAX;
    } else {
        res = 0.f;
        #pragma unroll
        for (int hh = 0; hh < HIi; hh++){
            float dot = 0.f;
            #pragma unroll
            for (int d = 0; d < DIi; d++) dot = fmaf(sq[tq][hh*DIi + d], sk[tk][d], dot);
            res += fmaxf(dot, 0.f) * sw[tq][hh];
        }
    }
    outI[(size_t)gq * SS + gk] = res;
}

// ---------------- per-row top-k (radix select + ascending-index tie-break) ----------------
__device__ __forceinline__ int blockScanInc(int v, int* scan, int t){
    __syncthreads();
    scan[t] = v; __syncthreads();
    for (int off = 1; off < 256; off <<= 1){
        int x = (t >= off) ? scan[t - off] : 0;
        __syncthreads();
        scan[t] += x;
        __syncthreads();
    }
    return scan[t];
}

__global__ void topk_kernel(const float* __restrict__ idxs, int* __restrict__ sel,
                            int* __restrict__ nsel){
    int q = blockIdx.x, t = threadIdx.x; // 256 threads
    int n = q + 1;
    if (n <= KTOPk){
        for (int k = t; k < n; k += 256) sel[(size_t)q * KTOPk + k] = k;
        if (t == 0) nsel[q] = n;
        return;
    }
    __shared__ unsigned su[SS];
    const float* row = idxs + (size_t)q * SS;
    for (int k = t; k < n; k += 256){
        unsigned b = __float_as_uint(row[k]);
        su[k] = (b & 0x80000000u) ? ~b : (b | 0x80000000u);
    }
    __syncthreads();

    __shared__ int hist[256];
    __shared__ int sdig, srem;
    unsigned prefix = 0, mask = 0;
    int remaining = KTOPk;
    for (int pass = 0; pass < 4; pass++){
        int shift = 24 - pass * 8;
        hist[t] = 0;
        __syncthreads();
        for (int k = t; k < n; k += 256){
            unsigned u = su[k];
            if ((u & mask) == prefix) atomicAdd(&hist[(u >> shift) & 255], 1);
        }
        __syncthreads();
        if (t == 0){
            int rem = remaining, d;
            for (d = 255; d > 0; d--){
                if (hist[d] >= rem) break;
                rem -= hist[d];
            }
            sdig = d; srem = rem;
        }
        __syncthreads();
        prefix |= ((unsigned)sdig) << shift;
        mask   |= (255u << shift);
        remaining = srem;
        __syncthreads();
    }
    unsigned uthr = prefix;
    int T = remaining;

    __shared__ int scan[256];
    __shared__ int base_eq, base_sel;
    if (t == 0){ base_eq = 0; base_sel = 0; }
    __syncthreads();
    for (int c0 = 0; c0 < n; c0 += 256){
        int k = c0 + t;
        unsigned u = (k < n) ? su[k] : 0u;
        int is_gt = (k < n) && (u > uthr);
        int is_eq = (k < n) && (u == uthr);
        int eq_inc = blockScanInc(is_eq, scan, t);
        int tie_rank = base_eq + (eq_inc - is_eq);
        int chunk_eq = scan[255];
        __syncthreads();
        int is_sel = is_gt || (is_eq && tie_rank < T);
        int sel_inc = blockScanInc(is_sel, scan, t);
        int pos = base_sel + (sel_inc - is_sel);
        int chunk_sel = scan[255];
        if (is_sel) sel[(size_t)q * KTOPk + pos] = k;
        __syncthreads();
        if (t == 0){ base_eq += chunk_eq; base_sel += chunk_sel; }
        __syncthreads();
    }
    if (t == 0) nsel[q] = KTOPk;
}

// ---------------- sparse attention over selected keys ----------------
__global__ void __launch_bounds__(128)
attn_kernel(const float* __restrict__ qf, const float* __restrict__ kf,
            const float* __restrict__ kv, const int* __restrict__ sel,
            const int* __restrict__ nsel, float* __restrict__ o){
    int s = blockIdx.x, h = blockIdx.y;
    int t = threadIdx.x;            // 128
    int w = t >> 5, lane = t & 31;
    int ns = nsel[s];

    __shared__ float qs[QD];
    __shared__ float lg[KTOPk];
    __shared__ int   ksm[KTOPk];
    __shared__ float red[4];

    for (int i = t; i < QD; i += 128) qs[i] = qf[(size_t)s * (NH*QD) + h * QD + i];
    for (int i = t; i < ns; i += 128) ksm[i] = sel[(size_t)s * KTOPk + i];
    __syncthreads();

    const float scale = 0.07216878364870323f; // 1/sqrt(192)
    for (int j = w; j < ns; j += 4){
        const float* kp = kf + (size_t)ksm[j] * (NH*QD) + h * QD;
        float d = 0.f;
        #pragma unroll
        for (int e = 0; e < 6; e++) d = fmaf(qs[lane + e*32], kp[lane + e*32], d);
        #pragma unroll
        for (int off = 16; off; off >>= 1) d += __shfl_xor_sync(0xffffffffu, d, off);
        if (lane == 0) lg[j] = d * scale;
    }
    __syncthreads();

    float m = -FLT_MAX;
    for (int i = t; i < ns; i += 128) m = fmaxf(m, lg[i]);
    #pragma unroll
    for (int off = 16; off; off >>= 1) m = fmaxf(m, __shfl_xor_sync(0xffffffffu, m, off));
    if (lane == 0) red[w] = m;
    __syncthreads();
    m = fmaxf(fmaxf(red[0], red[1]), fmaxf(red[2], red[3]));
    __syncthreads();

    float psum = 0.f;
    for (int i = t; i < ns; i += 128){
        float p = expf(lg[i] - m);
        lg[i] = p;
        psum += p;
    }
    #pragma unroll
    for (int off = 16; off; off >>= 1) psum += __shfl_xor_sync(0xffffffffu, psum, off);
    if (lane == 0) red[w] = psum;
    __syncthreads();
    float tot = red[0] + red[1] + red[2] + red[3];
    float inv = 1.f / tot;

    const float* vb = kv + h * KVD + DN;
    float a0 = 0.f, a1 = 0.f, a2 = 0.f, a3 = 0.f;
    int j = 0;
    for (; j + 3 < ns; j += 4){
        a0 = fmaf(lg[j+0], vb[(size_t)ksm[j+0] * (NH*KVD) + t], a0);
        a1 = fmaf(lg[j+1], vb[(size_t)ksm[j+1] * (NH*KVD) + t], a1);
        a2 = fmaf(lg[j+2], vb[(size_t)ksm[j+2] * (NH*KVD) + t], a2);
        a3 = fmaf(lg[j+3], vb[(size_t)ksm[j+3] * (NH*KVD) + t], a3);
    }
    for (; j < ns; j++) a0 = fmaf(lg[j], vb[(size_t)ksm[j] * (NH*KVD) + t], a0);
    o[(size_t)s * (NH*DVp) + h * DVp + t] = ((a0 + a1) + (a2 + a3)) * inv;
}

// ---------------- MoE gating ----------------
__global__ void zero_kernel(int* cnt, float* ps){
    if (threadIdx.x < NE){ cnt[threadIdx.x] = 0; ps[threadIdx.x] = 0.f; }
}

__global__ void gate_kernel(const float* __restrict__ rl, int* __restrict__ cnt,
                            float* __restrict__ ps, int* __restrict__ list,
                            float* __restrict__ gate){
    int tk = blockIdx.x * 256 + threadIdx.x;
    if (tk >= SS) return;
    float l[NE], p[NE];
    float mx = -FLT_MAX;
    #pragma unroll
    for (int e = 0; e < NE; e++){ l[e] = rl[(size_t)tk * NE + e]; mx = fmaxf(mx, l[e]); }
    float sum = 0.f;
    #pragma unroll
    for (int e = 0; e < NE; e++){ p[e] = expf(l[e] - mx); sum += p[e]; }
    #pragma unroll
    for (int e = 0; e < NE; e++) p[e] /= sum;
    int i0 = 0;
    #pragma unroll
    for (int e = 1; e < NE; e++) if (p[e] > p[i0]) i0 = e;
    int i1 = -1;
    #pragma unroll
    for (int e = 0; e < NE; e++) if (e != i0 && (i1 < 0 || p[e] > p[i1])) i1 = e;
    float g0 = p[i0], g1 = p[i1], gs = g0 + g1;
    int pos0 = atomicAdd(&cnt[i0], 1);
    list[i0 * SS + pos0] = tk; gate[i0 * SS + pos0] = g0 / gs;
    int pos1 = atomicAdd(&cnt[i1], 1);
    list[i1 * SS + pos1] = tk; gate[i1 * SS + pos1] = g1 / gs;
    #pragma unroll
    for (int e = 0; e < NE; e++) atomicAdd(&ps[e], p[e]);
}

__global__ void aux_kernel(const int* __restrict__ cnt, const float* __restrict__ ps,
                           float* __restrict__ outAux){
    float a = 0.f;
    for (int e = 0; e < NE; e++)
        a += ((float)cnt[e] / (float)SS) * (ps[e] / (float)SS);
    *outAux = (float)NE * a;
}

// ---------------- host ----------------
extern "C" void kernel_launch(void* const* d_in, const int* in_sizes, int n_in,
                              void* d_out, int out_size){
    const float* x    = (const float*)d_in[0];
    const float* n1w  = (const float*)d_in[1];
    const float* n2w  = (const float*)d_in[2];
    const float* kvnw = (const float*)d_in[3];
    const float* Wq   = (const float*)d_in[4];
    const float* Wkva = (const float*)d_in[5];
    const float* Wkvb = (const float*)d_in[6];
    const float* Wo   = (const float*)d_in[7];
    const float* Wiq  = (const float*)d_in[8];
    const float* Wik  = (const float*)d_in[9];
    const float* Wiw  = (const float*)d_in[10];
    const float* Wr   = (const float*)d_in[11];
    const float* W1   = (const float*)d_in[12];
    const float* b1   = (const float*)d_in[13];
    const float* W2   = (const float*)d_in[14];
    const float* b2   = (const float*)d_in[15];

    float* out     = (float*)d_out;
    float* out_x   = out;
    float* out_aux = out + (size_t)SS * DD;
    float* out_idx = out + (size_t)SS * DD + 1;

    float *ph, *pq, *pckv, *pc, *pkv, *pkf, *pqi, *pki, *pwt, *po, *px2, *ph2, *prl, *phid, *pgate, *pps;
    int *psel, *pnsel, *pcnt, *plist;
    cudaGetSymbolAddress((void**)&ph,   g_h);
    cudaGetSymbolAddress((void**)&pq,   g_q);
    cudaGetSymbolAddress((void**)&pckv, g_ckv);
    cudaGetSymbolAddress((void**)&pc,   g_c);
    cudaGetSymbolAddress((void**)&pkv,  g_kv);
    cudaGetSymbolAddress((void**)&pkf,  g_kf);
    cudaGetSymbolAddress((void**)&pqi,  g_qi);
    cudaGetSymbolAddress((void**)&pki,  g_ki);
    cudaGetSymbolAddress((void**)&pwt,  g_wt);
    cudaGetSymbolAddress((void**)&po,   g_o);
    cudaGetSymbolAddress((void**)&px2,  g_x2);
    cudaGetSymbolAddress((void**)&ph2,  g_h2);
    cudaGetSymbolAddress((void**)&prl,  g_rl);
    cudaGetSymbolAddress((void**)&phid, g_hid);
    cudaGetSymbolAddress((void**)&pgate,g_gate);
    cudaGetSymbolAddress((void**)&pps,  g_ps);
    cudaGetSymbolAddress((void**)&psel, g_sel);
    cudaGetSymbolAddress((void**)&pnsel,g_nsel);
    cudaGetSymbolAddress((void**)&pcnt, g_cnt);
    cudaGetSymbolAddress((void**)&plist,g_list);

    // 1. h = rms(x, norm1_w)
    rms_kernel<<<SS, 256>>>(x, DD, DD, n1w, ph, DD);
    // 2. q = h @ Wq  (tf32)
    tgemm_k<0,false><<<dim3(24,16), 256>>>(ph, Wq, pq, SS, NH*QD, DD, nullptr,nullptr,nullptr,nullptr,nullptr);
    // 3. ckv = h @ Wkva  (tf32)
    tgemm_k<0,false><<<dim3(5,16), 256>>>(ph, Wkva, pckv, SS, RDIM+DRp, DD, nullptr,nullptr,nullptr,nullptr,nullptr);
    // 4. c = rms(ckv[:, :R], kv_norm_w)
    rms_kernel<<<SS, 256>>>(pckv, RDIM+DRp, RDIM, kvnw, pc, RDIM);
    // 5. kv = c @ Wkvb  (tf32)
    tgemm_k<0,false><<<dim3(32,16), 256>>>(pc, Wkvb, pkv, SS, NH*KVD, RDIM, nullptr,nullptr,nullptr,nullptr,nullptr);
    // 6. rope on q (in place)
    ropeq_kernel<<<dim3(SS, NH), 64>>>(pq);
    // 7. k_full
    buildkf_kernel<<<SS, 256>>>(pkv, pckv, pkf);
    // 8. indexer projections (fp32 — keep top-k selection bit-identical)
    sgemm_k<0,false><<<dim3(2,16), 256>>>(ph, Wiq, pqi, SS, HIi*DIi, DD, nullptr,nullptr,nullptr,nullptr,nullptr);
    sgemm_k<0,false><<<dim3(1,16), 256>>>(ph, Wik, pki, SS, DIi, DD, nullptr,nullptr,nullptr,nullptr,nullptr);
    sgemm_k<0,false><<<dim3(1,16), 256>>>(ph, Wiw, pwt, SS, HIi, DD, nullptr,nullptr,nullptr,nullptr,nullptr);
    // 9. idx_scores (written straight into output)
    idx_kernel<<<dim3(128,128), 256>>>(pqi, pki, pwt, out_idx);
    // 10. per-row top-k selection
    topk_kernel<<<SS, 256>>>(out_idx, psel, pnsel);
    // 11. sparse attention
    attn_kernel<<<dim3(SS, NH), 128>>>(pq, pkf, pkv, psel, pnsel, po);
    // 12. x2 = x + o @ Wo  (tf32)
    tgemm_k<1,false><<<dim3(16,16), 256>>>(po, Wo, px2, SS, DD, NH*DVp, nullptr,nullptr,nullptr, x, nullptr);
    // 13. h2 = rms(x2, norm2_w)
    rms_kernel<<<SS, 256>>>(px2, DD, DD, n2w, ph2, DD);
    // 14. router logits (fp32 — keep expert selection bit-identical)
    sgemm_k<0,false><<<dim3(1,16), 256>>>(ph2, Wr, prl, SS, NE, DD, nullptr,nullptr,nullptr,nullptr,nullptr);
    // 15. gating
    zero_kernel<<<1, 32>>>(pcnt, pps);
    gate_kernel<<<(SS+255)/256, 256>>>(prl, pcnt, pps, plist, pgate);
    aux_kernel<<<1, 1>>>(pcnt, pps, out_aux);
    // 16. init output x region with x2, then scatter-add MoE  (tf32)
    cudaMemcpyAsync(out_x, px2, sizeof(float)*(size_t)SS*DD, cudaMemcpyDeviceToDevice, 0);
    for (int e = 0; e < NE; e++){
        // hid = gelu(gather(h2) @ W1[e] + b1[e])
        tgemm_k<2,true><<<dim3(64,16), 256>>>(ph2, W1 + (size_t)e*DD*DFF, phid,
                                              SS, DFF, DD,
                                              plist + e*SS, pcnt + e,
                                              b1 + (size_t)e*DFF, nullptr, nullptr);
        // out[tok] += gate * (hid @ W2[e] + b2[e])
        tgemm_k<3,false><<<dim3(16,16), 256>>>(phid, W2 + (size_t)e*DFF*DD, out_x,
                                               SS, DD, DFF,
                                               plist + e*SS, pcnt + e,
                                               b2 + (size_t)e*DD, nullptr, pgate + e*SS);
    }
}